// round 3
// baseline (speedup 1.0000x reference)
#include <cuda_runtime.h>
#include <cuda_fp16.h>
#include <mma.h>
#include <math.h>
#include <stdint.h>

using namespace nvcuda;

#define NW 10000
#define HIDW 64

// ---------------- device scratch (static, allocation-free) ----------------
__device__ __align__(16) __half g_A16[100000000];   // adjacency fp16, scaled x256
__device__ __align__(16) __half g_cat1[NW * 384];   // [u0 | A u0 | 2A^2u0 - u0]
__device__ __align__(16) __half g_cat2[NW * 384];
__device__ float g_h[NW * HIDW];
__device__ float g_u[NW * HIDW];
__device__ float g_x[NW];

// ---------------- A conversion ----------------
__global__ void convA(const float* __restrict__ A) {
    size_t i = (size_t)blockIdx.x * blockDim.x + threadIdx.x;
    size_t stride = (size_t)gridDim.x * blockDim.x;
    for (size_t j = i; j < 25000000ull; j += stride) {
        float4 f = ((const float4*)A)[j];
        __half2 a = __floats2half2_rn(f.x * 256.f, f.y * 256.f);
        __half2 b = __floats2half2_rn(f.z * 256.f, f.w * 256.f);
        ((__half2*)g_A16)[2 * j]     = a;
        ((__half2*)g_A16)[2 * j + 1] = b;
    }
}

__global__ void initState() {
    int idx = blockIdx.x * blockDim.x + threadIdx.x;
    if (idx < NW * HIDW) g_h[idx] = 0.f;
    if (idx < NW) g_x[idx] = 0.f;
}

// ---------------- builds ----------------
__global__ void encBuild(const float* __restrict__ inputs, const float* __restrict__ W_emb,
                         const float* __restrict__ b_emb, int t) {
    int idx = blockIdx.x * blockDim.x + threadIdx.x;
    if (idx >= NW * 128) return;
    int row = idx >> 7, c = idx & 127;
    float v;
    if (c < 64) v = inputs[row * 12 + t] * W_emb[c] + b_emb[c];
    else        v = g_h[row * 64 + (c - 64)];
    g_cat1[(size_t)row * 384 + c] = __float2half(v);
}

__global__ void decBuild() {
    int idx = blockIdx.x * blockDim.x + threadIdx.x;
    if (idx >= NW * 128) return;
    int row = idx >> 7, c = idx & 127;
    float v = 0.f;
    if (c == 0)      v = g_x[row];
    else if (c < 65) v = g_h[row * 64 + (c - 1)];
    g_cat1[(size_t)row * 384 + c] = __float2half(v);
}

// ---------------- big GEMM: A(10000x10000,fp16 x256) @ cat[:,bcol:bcol+128] ----------------
// BM=64, BN=64, BK=32, 8 warps (4x2), warp tile 16x32. grid (157, 2).
// ucol >= 0 => out = 2*(acc/256) - cat[:,ucol+...]   (Chebyshev), else out = acc/256.
__global__ void __launch_bounds__(256, 2) bigGemm(__half* cat, int bcol, int ccol, int ucol) {
    __shared__ __align__(16) __half As[64][40];
    __shared__ __align__(16) __half Bs[32][72];
    __shared__ float Cs[8][512];
    const int tid = threadIdx.x, warp = tid >> 5, lane = tid & 31;
    const int wm = warp & 3, wn = warp >> 2;
    const int row0 = blockIdx.x * 64, col0 = blockIdx.y * 64;

    wmma::fragment<wmma::accumulator, 16, 16, 16, float> acc[2];
    wmma::fill_fragment(acc[0], 0.f);
    wmma::fill_fragment(acc[1], 0.f);

    const int ar = tid >> 2, ac = (tid & 3) << 3;   // A: 64 rows x 4 chunks of 8
    const int br = tid >> 3, bc = (tid & 7) << 3;   // B: 32 rows x 8 chunks of 8

    for (int k0 = 0; k0 < NW; k0 += 32) {
        float4 av = make_float4(0.f, 0.f, 0.f, 0.f);
        if (row0 + ar < NW && k0 + ac + 8 <= NW)
            av = *(const float4*)(g_A16 + (size_t)(row0 + ar) * NW + k0 + ac);
        *(float4*)&As[ar][ac] = av;

        float4 bv = make_float4(0.f, 0.f, 0.f, 0.f);
        if (k0 + br < NW)
            bv = *(const float4*)(cat + (size_t)(k0 + br) * 384 + bcol + col0 + bc);
        *(float4*)&Bs[br][bc] = bv;
        __syncthreads();

#pragma unroll
        for (int kk = 0; kk < 32; kk += 16) {
            wmma::fragment<wmma::matrix_a, 16, 16, 16, __half, wmma::row_major> af;
            wmma::load_matrix_sync(af, &As[wm * 16][kk], 40);
#pragma unroll
            for (int j = 0; j < 2; j++) {
                wmma::fragment<wmma::matrix_b, 16, 16, 16, __half, wmma::row_major> bf;
                wmma::load_matrix_sync(bf, &Bs[kk][wn * 32 + j * 16], 72);
                wmma::mma_sync(acc[j], af, bf, acc[j]);
            }
        }
        __syncthreads();
    }

    wmma::store_matrix_sync(&Cs[warp][0],  acc[0], 32, wmma::mem_row_major);
    wmma::store_matrix_sync(&Cs[warp][16], acc[1], 32, wmma::mem_row_major);
    __syncwarp();

    const float sc = 1.f / 256.f;
    for (int r = 0; r < 16; r++) {
        int grow = row0 + wm * 16 + r;
        if (grow >= NW) break;
        int gcol = col0 + wn * 32 + lane;
        float v = Cs[warp][r * 32 + lane] * sc;
        if (ucol >= 0)
            v = 2.f * v - __half2float(cat[(size_t)grow * 384 + ucol + gcol]);
        cat[(size_t)grow * 384 + ccol + gcol] = __float2half(v);
    }
}

// ---------------- gate GEMM: cat1(10000x384 fp16) @ W(3D x 128 fp32) + bias -> sigmoid ----------------
// 8 rows per block, 128 threads (one per output col). D = per-group input dim (128 enc, 65 dec).
// Epilogue builds cat2 first 128 cols and writes u gate.
__global__ void wgemmGates(const __half* __restrict__ cat1, __half* __restrict__ cat2,
                           const float* __restrict__ W, const float* __restrict__ bias,
                           int D, int dec) {
    __shared__ __align__(16) __half cs[8][384];
    int tid = threadIdx.x;
    int row0 = blockIdx.x * 8;
    const float4* src = (const float4*)(cat1 + (size_t)row0 * 384);
    float4* dst = (float4*)&cs[0][0];
    for (int i = tid; i < 384; i += 128) dst[i] = src[i];
    __syncthreads();

    float v[8];
#pragma unroll
    for (int r = 0; r < 8; r++) v[r] = 0.f;
    int col = tid;
    for (int g = 0; g < 3; g++)
        for (int kk = 0; kk < D; kk++) {
            float w = W[(size_t)(g * D + kk) * 128 + col];
            int cc = g * 128 + kk;
#pragma unroll
            for (int r = 0; r < 8; r++) v[r] += __half2float(cs[r][cc]) * w;
        }
    float b = bias[col];
#pragma unroll
    for (int r = 0; r < 8; r++) {
        int row = row0 + r;
        float gate = 1.f / (1.f + __expf(-(v[r] + b)));
        if (col < 64) {
            float rh = gate * g_h[row * 64 + col];
            if (!dec) {
                cat2[(size_t)row * 384 + 64 + col] = __float2half(rh);
                cat2[(size_t)row * 384 + col] = cs[r][col];           // emb copy
            } else {
                cat2[(size_t)row * 384 + 1 + col] = __float2half(rh);
                if (col == 0) cat2[(size_t)row * 384] = cs[r][0];     // x copy
            }
        } else {
            g_u[row * 64 + (col - 64)] = gate;
            if (dec && col > 64) cat2[(size_t)row * 384 + col] = __float2half(0.f); // pad
        }
    }
}

// ---------------- candidate GEMM + GRU update: cat2 @ Wc(3D x 64) + bias -> tanh -> h ----------------
__global__ void wgemmCand(const __half* __restrict__ cat2, const float* __restrict__ W,
                          const float* __restrict__ bias, int D) {
    __shared__ __align__(16) __half cs[8][384];
    int tid = threadIdx.x;
    int row0 = blockIdx.x * 8;
    const float4* src = (const float4*)(cat2 + (size_t)row0 * 384);
    float4* dst = (float4*)&cs[0][0];
    for (int i = tid; i < 384; i += 64) dst[i] = src[i];
    __syncthreads();

    float v[8];
#pragma unroll
    for (int r = 0; r < 8; r++) v[r] = 0.f;
    int col = tid;
    for (int g = 0; g < 3; g++)
        for (int kk = 0; kk < D; kk++) {
            float w = W[(size_t)(g * D + kk) * 64 + col];
            int cc = g * 128 + kk;
#pragma unroll
            for (int r = 0; r < 8; r++) v[r] += __half2float(cs[r][cc]) * w;
        }
    float b = bias[col];
#pragma unroll
    for (int r = 0; r < 8; r++) {
        int row = row0 + r;
        float c = tanhf(v[r] + b);
        float u = g_u[row * 64 + col];
        float hOld = g_h[row * 64 + col];
        g_h[row * 64 + col] = u * hOld + (1.f - u) * c;
    }
}

// ---------------- prediction: out[:,t] = h @ W_pred + b_pred; feeds next decoder x ----------------
__global__ void predKernel(const float* __restrict__ Wp, const float* __restrict__ bp,
                           float* __restrict__ out, int t) {
    int gwarp = (blockIdx.x * blockDim.x + threadIdx.x) >> 5;
    int lane = threadIdx.x & 31;
    if (gwarp >= NW) return;
    float s = g_h[gwarp * 64 + lane] * Wp[lane] + g_h[gwarp * 64 + 32 + lane] * Wp[32 + lane];
#pragma unroll
    for (int o = 16; o; o >>= 1) s += __shfl_xor_sync(0xFFFFFFFFu, s, o);
    if (lane == 0) {
        float val = s + bp[0];
        out[gwarp * 12 + t] = val;
        g_x[gwarp] = val;
    }
}

// ---------------- launch ----------------
extern "C" void kernel_launch(void* const* d_in, const int* in_sizes, int n_in,
                              void* d_out, int out_size) {
    const float* inputs = (const float*)d_in[0];
    // d_in[1] = targets (unused)
    const float* adj    = (const float*)d_in[2];
    const float* W_emb  = (const float*)d_in[3];
    const float* b_emb  = (const float*)d_in[4];
    const float* Wg_e   = (const float*)d_in[5];
    const float* bg_e   = (const float*)d_in[6];
    const float* Wc_e   = (const float*)d_in[7];
    const float* bc_e   = (const float*)d_in[8];
    const float* Wg_d   = (const float*)d_in[9];
    const float* bg_d   = (const float*)d_in[10];
    const float* Wc_d   = (const float*)d_in[11];
    const float* bc_d   = (const float*)d_in[12];
    const float* W_pred = (const float*)d_in[13];
    const float* b_pred = (const float*)d_in[14];
    float* out = (float*)d_out;

    __half *cat1, *cat2;
    cudaGetSymbolAddress((void**)&cat1, g_cat1);
    cudaGetSymbolAddress((void**)&cat2, g_cat2);

    convA<<<1184, 256>>>(adj);
    initState<<<(NW * HIDW + 255) / 256, 256>>>();

    dim3 bg_grid(157, 2);
    int build_grid = (NW * 128 + 255) / 256;

    // encoder
    for (int t = 0; t < 12; t++) {
        encBuild<<<build_grid, 256>>>(inputs, W_emb, b_emb, t);
        bigGemm<<<bg_grid, 256>>>(cat1, 0, 128, -1);
        bigGemm<<<bg_grid, 256>>>(cat1, 128, 256, 0);
        wgemmGates<<<NW / 8, 128>>>(cat1, cat2, Wg_e, bg_e, 128, 0);
        bigGemm<<<bg_grid, 256>>>(cat2, 0, 128, -1);
        bigGemm<<<bg_grid, 256>>>(cat2, 128, 256, 0);
        wgemmCand<<<NW / 8, 64>>>(cat2, Wc_e, bc_e, 128);
    }
    // decoder
    for (int t = 0; t < 12; t++) {
        decBuild<<<build_grid, 256>>>();
        bigGemm<<<bg_grid, 256>>>(cat1, 0, 128, -1);
        bigGemm<<<bg_grid, 256>>>(cat1, 128, 256, 0);
        wgemmGates<<<NW / 8, 128>>>(cat1, cat2, Wg_d, bg_d, 65, 1);
        bigGemm<<<bg_grid, 256>>>(cat2, 0, 128, -1);
        bigGemm<<<bg_grid, 256>>>(cat2, 128, 256, 0);
        wgemmCand<<<NW / 8, 64>>>(cat2, Wc_d, bc_d, 65);
        predKernel<<<(NW + 3) / 4, 128>>>(W_pred, b_pred, out, t);
    }
}

// round 4
// speedup vs baseline: 1.0008x; 1.0008x over previous
#include <cuda_runtime.h>
#include <cuda_fp16.h>
#include <mma.h>
#include <math.h>
#include <stdint.h>

using namespace nvcuda;

#define NW 10000
#define HIDW 64

// ---------------- device scratch (static, allocation-free) ----------------
__device__ __align__(16) __half g_A16[100000000];   // adjacency fp16, scaled x256
__device__ __align__(16) __half g_cat1[NW * 384];   // [u0 | A u0 | 2A^2u0 - u0]
__device__ __align__(16) __half g_cat2[NW * 384];
__device__ float g_h[NW * HIDW];
__device__ float g_u[NW * HIDW];
__device__ float g_x[NW];

// ---------------- A conversion ----------------
__global__ void convA(const float* __restrict__ A) {
    size_t i = (size_t)blockIdx.x * blockDim.x + threadIdx.x;
    size_t stride = (size_t)gridDim.x * blockDim.x;
    for (size_t j = i; j < 25000000ull; j += stride) {
        float4 f = ((const float4*)A)[j];
        __half2 a = __floats2half2_rn(f.x * 256.f, f.y * 256.f);
        __half2 b = __floats2half2_rn(f.z * 256.f, f.w * 256.f);
        ((__half2*)g_A16)[2 * j]     = a;
        ((__half2*)g_A16)[2 * j + 1] = b;
    }
}

__global__ void initState() {
    int idx = blockIdx.x * blockDim.x + threadIdx.x;
    if (idx < NW * HIDW) g_h[idx] = 0.f;
    if (idx < NW) g_x[idx] = 0.f;
}

// ---------------- builds ----------------
__global__ void encBuild(const float* __restrict__ inputs, const float* __restrict__ W_emb,
                         const float* __restrict__ b_emb, int t) {
    int idx = blockIdx.x * blockDim.x + threadIdx.x;
    if (idx >= NW * 128) return;
    int row = idx >> 7, c = idx & 127;
    float v;
    if (c < 64) v = inputs[row * 12 + t] * W_emb[c] + b_emb[c];
    else        v = g_h[row * 64 + (c - 64)];
    g_cat1[(size_t)row * 384 + c] = __float2half(v);
}

__global__ void decBuild() {
    int idx = blockIdx.x * blockDim.x + threadIdx.x;
    if (idx >= NW * 128) return;
    int row = idx >> 7, c = idx & 127;
    float v = 0.f;
    if (c == 0)      v = g_x[row];
    else if (c < 65) v = g_h[row * 64 + (c - 1)];
    g_cat1[(size_t)row * 384 + c] = __float2half(v);
}

// ---------------- big GEMM: A(10000x10000,fp16 x256) @ cat[:,bcol:bcol+128] ----------------
// BM=64, BN=64, BK=32, 8 warps (4x2), warp tile 16x32. grid (157, 2).
// ucol >= 0 => out = 2*(acc/256) - cat[:,ucol+...]   (Chebyshev), else out = acc/256.
__global__ void __launch_bounds__(256, 2) bigGemm(__half* cat, int bcol, int ccol, int ucol) {
    __shared__ __align__(16) __half As[64][40];
    __shared__ __align__(16) __half Bs[32][72];
    __shared__ float Cs[8][512];
    const int tid = threadIdx.x, warp = tid >> 5, lane = tid & 31;
    const int wm = warp & 3, wn = warp >> 2;
    const int row0 = blockIdx.x * 64, col0 = blockIdx.y * 64;

    wmma::fragment<wmma::accumulator, 16, 16, 16, float> acc[2];
    wmma::fill_fragment(acc[0], 0.f);
    wmma::fill_fragment(acc[1], 0.f);

    const int ar = tid >> 2, ac = (tid & 3) << 3;   // A: 64 rows x 4 chunks of 8
    const int br = tid >> 3, bc = (tid & 7) << 3;   // B: 32 rows x 8 chunks of 8

    for (int k0 = 0; k0 < NW; k0 += 32) {
        float4 av = make_float4(0.f, 0.f, 0.f, 0.f);
        if (row0 + ar < NW && k0 + ac + 8 <= NW)
            av = *(const float4*)(g_A16 + (size_t)(row0 + ar) * NW + k0 + ac);
        *(float4*)&As[ar][ac] = av;

        float4 bv = make_float4(0.f, 0.f, 0.f, 0.f);
        if (k0 + br < NW)
            bv = *(const float4*)(cat + (size_t)(k0 + br) * 384 + bcol + col0 + bc);
        *(float4*)&Bs[br][bc] = bv;
        __syncthreads();

#pragma unroll
        for (int kk = 0; kk < 32; kk += 16) {
            wmma::fragment<wmma::matrix_a, 16, 16, 16, __half, wmma::row_major> af;
            wmma::load_matrix_sync(af, &As[wm * 16][kk], 40);
#pragma unroll
            for (int j = 0; j < 2; j++) {
                wmma::fragment<wmma::matrix_b, 16, 16, 16, __half, wmma::row_major> bf;
                wmma::load_matrix_sync(bf, &Bs[kk][wn * 32 + j * 16], 72);
                wmma::mma_sync(acc[j], af, bf, acc[j]);
            }
        }
        __syncthreads();
    }

    wmma::store_matrix_sync(&Cs[warp][0],  acc[0], 32, wmma::mem_row_major);
    wmma::store_matrix_sync(&Cs[warp][16], acc[1], 32, wmma::mem_row_major);
    __syncwarp();

    const float sc = 1.f / 256.f;
    for (int r = 0; r < 16; r++) {
        int grow = row0 + wm * 16 + r;
        if (grow >= NW) break;
        int gcol = col0 + wn * 32 + lane;
        float v = Cs[warp][r * 32 + lane] * sc;
        if (ucol >= 0)
            v = 2.f * v - __half2float(cat[(size_t)grow * 384 + ucol + gcol]);
        cat[(size_t)grow * 384 + ccol + gcol] = __float2half(v);
    }
}

// ---------------- gate GEMM: cat1(10000x384 fp16) @ W(3D x 128 fp32) + bias -> sigmoid ----------------
// 8 rows per block, 128 threads (one per output col). D = per-group input dim (128 enc, 65 dec).
// Epilogue builds cat2 first 128 cols and writes u gate.
__global__ void wgemmGates(const __half* __restrict__ cat1, __half* __restrict__ cat2,
                           const float* __restrict__ W, const float* __restrict__ bias,
                           int D, int dec) {
    __shared__ __align__(16) __half cs[8][384];
    int tid = threadIdx.x;
    int row0 = blockIdx.x * 8;
    const float4* src = (const float4*)(cat1 + (size_t)row0 * 384);
    float4* dst = (float4*)&cs[0][0];
    for (int i = tid; i < 384; i += 128) dst[i] = src[i];
    __syncthreads();

    float v[8];
#pragma unroll
    for (int r = 0; r < 8; r++) v[r] = 0.f;
    int col = tid;
    for (int g = 0; g < 3; g++)
        for (int kk = 0; kk < D; kk++) {
            float w = W[(size_t)(g * D + kk) * 128 + col];
            int cc = g * 128 + kk;
#pragma unroll
            for (int r = 0; r < 8; r++) v[r] += __half2float(cs[r][cc]) * w;
        }
    float b = bias[col];
#pragma unroll
    for (int r = 0; r < 8; r++) {
        int row = row0 + r;
        float gate = 1.f / (1.f + __expf(-(v[r] + b)));
        if (col < 64) {
            float rh = gate * g_h[row * 64 + col];
            if (!dec) {
                cat2[(size_t)row * 384 + 64 + col] = __float2half(rh);
                cat2[(size_t)row * 384 + col] = cs[r][col];           // emb copy
            } else {
                cat2[(size_t)row * 384 + 1 + col] = __float2half(rh);
                if (col == 0) cat2[(size_t)row * 384] = cs[r][0];     // x copy
            }
        } else {
            g_u[row * 64 + (col - 64)] = gate;
            if (dec && col > 64) cat2[(size_t)row * 384 + col] = __float2half(0.f); // pad
        }
    }
}

// ---------------- candidate GEMM + GRU update: cat2 @ Wc(3D x 64) + bias -> tanh -> h ----------------
__global__ void wgemmCand(const __half* __restrict__ cat2, const float* __restrict__ W,
                          const float* __restrict__ bias, int D) {
    __shared__ __align__(16) __half cs[8][384];
    int tid = threadIdx.x;
    int row0 = blockIdx.x * 8;
    const float4* src = (const float4*)(cat2 + (size_t)row0 * 384);
    float4* dst = (float4*)&cs[0][0];
    for (int i = tid; i < 384; i += 64) dst[i] = src[i];
    __syncthreads();

    float v[8];
#pragma unroll
    for (int r = 0; r < 8; r++) v[r] = 0.f;
    int col = tid;
    for (int g = 0; g < 3; g++)
        for (int kk = 0; kk < D; kk++) {
            float w = W[(size_t)(g * D + kk) * 64 + col];
            int cc = g * 128 + kk;
#pragma unroll
            for (int r = 0; r < 8; r++) v[r] += __half2float(cs[r][cc]) * w;
        }
    float b = bias[col];
#pragma unroll
    for (int r = 0; r < 8; r++) {
        int row = row0 + r;
        float c = tanhf(v[r] + b);
        float u = g_u[row * 64 + col];
        float hOld = g_h[row * 64 + col];
        g_h[row * 64 + col] = u * hOld + (1.f - u) * c;
    }
}

// ---------------- prediction: out[:,t] = h @ W_pred + b_pred; feeds next decoder x ----------------
__global__ void predKernel(const float* __restrict__ Wp, const float* __restrict__ bp,
                           float* __restrict__ out, int t) {
    int gwarp = (blockIdx.x * blockDim.x + threadIdx.x) >> 5;
    int lane = threadIdx.x & 31;
    if (gwarp >= NW) return;
    float s = g_h[gwarp * 64 + lane] * Wp[lane] + g_h[gwarp * 64 + 32 + lane] * Wp[32 + lane];
#pragma unroll
    for (int o = 16; o; o >>= 1) s += __shfl_xor_sync(0xFFFFFFFFu, s, o);
    if (lane == 0) {
        float val = s + bp[0];
        out[gwarp * 12 + t] = val;
        g_x[gwarp] = val;
    }
}

// ---------------- launch ----------------
extern "C" void kernel_launch(void* const* d_in, const int* in_sizes, int n_in,
                              void* d_out, int out_size) {
    const float* inputs = (const float*)d_in[0];
    // d_in[1] = targets (unused)
    const float* adj    = (const float*)d_in[2];
    const float* W_emb  = (const float*)d_in[3];
    const float* b_emb  = (const float*)d_in[4];
    const float* Wg_e   = (const float*)d_in[5];
    const float* bg_e   = (const float*)d_in[6];
    const float* Wc_e   = (const float*)d_in[7];
    const float* bc_e   = (const float*)d_in[8];
    const float* Wg_d   = (const float*)d_in[9];
    const float* bg_d   = (const float*)d_in[10];
    const float* Wc_d   = (const float*)d_in[11];
    const float* bc_d   = (const float*)d_in[12];
    const float* W_pred = (const float*)d_in[13];
    const float* b_pred = (const float*)d_in[14];
    float* out = (float*)d_out;

    __half *cat1, *cat2;
    cudaGetSymbolAddress((void**)&cat1, g_cat1);
    cudaGetSymbolAddress((void**)&cat2, g_cat2);

    convA<<<1184, 256>>>(adj);
    initState<<<(NW * HIDW + 255) / 256, 256>>>();

    dim3 bg_grid(157, 2);
    int build_grid = (NW * 128 + 255) / 256;

    // encoder
    for (int t = 0; t < 12; t++) {
        encBuild<<<build_grid, 256>>>(inputs, W_emb, b_emb, t);
        bigGemm<<<bg_grid, 256>>>(cat1, 0, 128, -1);
        bigGemm<<<bg_grid, 256>>>(cat1, 128, 256, 0);
        wgemmGates<<<NW / 8, 128>>>(cat1, cat2, Wg_e, bg_e, 128, 0);
        bigGemm<<<bg_grid, 256>>>(cat2, 0, 128, -1);
        bigGemm<<<bg_grid, 256>>>(cat2, 128, 256, 0);
        wgemmCand<<<NW / 8, 64>>>(cat2, Wc_e, bc_e, 128);
    }
    // decoder
    for (int t = 0; t < 12; t++) {
        decBuild<<<build_grid, 256>>>();
        bigGemm<<<bg_grid, 256>>>(cat1, 0, 128, -1);
        bigGemm<<<bg_grid, 256>>>(cat1, 128, 256, 0);
        wgemmGates<<<NW / 8, 128>>>(cat1, cat2, Wg_d, bg_d, 65, 1);
        bigGemm<<<bg_grid, 256>>>(cat2, 0, 128, -1);
        bigGemm<<<bg_grid, 256>>>(cat2, 128, 256, 0);
        wgemmCand<<<NW / 8, 64>>>(cat2, Wc_d, bc_d, 65);
        predKernel<<<(NW + 3) / 4, 128>>>(W_pred, b_pred, out, t);
    }
}

// round 5
// speedup vs baseline: 1.4170x; 1.4159x over previous
#include <cuda_runtime.h>
#include <cuda_fp16.h>
#include <mma.h>
#include <math.h>
#include <stdint.h>

using namespace nvcuda;

#define NW 10000
#define HIDW 64
#define STAGES 4
#define A_STAGE 2560   /* halves: 64 rows x 40 */
#define B_STAGE 4352   /* halves: 32 rows x 136 */

// ---------------- device scratch (static, allocation-free) ----------------
__device__ __align__(16) __half g_A16[100000000];   // adjacency fp16, scaled x256
__device__ __align__(16) __half g_cat1[NW * 384];
__device__ __align__(16) __half g_cat2[NW * 384];
__device__ float g_h[NW * HIDW];
__device__ float g_u[NW * HIDW];
__device__ float g_x[NW];

// ---------------- A conversion ----------------
__global__ void convA(const float* __restrict__ A) {
    size_t i = (size_t)blockIdx.x * blockDim.x + threadIdx.x;
    size_t stride = (size_t)gridDim.x * blockDim.x;
    for (size_t j = i; j < 25000000ull; j += stride) {
        float4 f = ((const float4*)A)[j];
        __half2 a = __floats2half2_rn(f.x * 256.f, f.y * 256.f);
        __half2 b = __floats2half2_rn(f.z * 256.f, f.w * 256.f);
        ((__half2*)g_A16)[2 * j]     = a;
        ((__half2*)g_A16)[2 * j + 1] = b;
    }
}

__global__ void initState() {
    int idx = blockIdx.x * blockDim.x + threadIdx.x;
    if (idx < NW * HIDW) g_h[idx] = 0.f;
    if (idx < NW) g_x[idx] = 0.f;
}

// ---------------- builds ----------------
__global__ void encBuild(const float* __restrict__ inputs, const float* __restrict__ W_emb,
                         const float* __restrict__ b_emb, int t) {
    int idx = blockIdx.x * blockDim.x + threadIdx.x;
    if (idx >= NW * 128) return;
    int row = idx >> 7, c = idx & 127;
    float v;
    if (c < 64) v = inputs[row * 12 + t] * W_emb[c] + b_emb[c];
    else        v = g_h[row * 64 + (c - 64)];
    g_cat1[(size_t)row * 384 + c] = __float2half(v);
}

__global__ void decBuild() {
    int idx = blockIdx.x * blockDim.x + threadIdx.x;
    if (idx >= NW * 128) return;
    int row = idx >> 7, c = idx & 127;
    float v = 0.f;
    if (c == 0)      v = g_x[row];
    else if (c < 65) v = g_h[row * 64 + (c - 1)];
    g_cat1[(size_t)row * 384 + c] = __float2half(v);
}

// ---------------- cp.async helper ----------------
__device__ __forceinline__ void cpa16(__half* s, const __half* g, bool v) {
    uint32_t sa = (uint32_t)__cvta_generic_to_shared(s);
    int n = v ? 16 : 0;
    asm volatile("cp.async.cg.shared.global [%0], [%1], 16, %2;\n" :: "r"(sa), "l"(g), "r"(n));
}

// ---------------- big GEMM: A(10000x10000 fp16 x256) @ cat[:, bcol:bcol+128] ----------------
// BM=64, BN=128, BK=32, 4-stage cp.async pipeline, 8 warps (4x2), warp tile 16x64.
// grid = 157 blocks, all resident in one wave (2 CTA/SM).
// ucol >= 0 => out = 2*(acc/256) - cat[:,ucol+...] (Chebyshev), else out = acc/256.
__global__ void __launch_bounds__(256, 2) bigGemm(__half* cat, int bcol, int ccol, int ucol) {
    extern __shared__ __align__(16) char raw[];
    __half* As = (__half*)raw;                           // [STAGES][64][40]
    __half* Bs = (__half*)(raw + STAGES * A_STAGE * 2);  // [STAGES][32][136]

    const int tid = threadIdx.x, warp = tid >> 5, lane = tid & 31;
    const int wm = warp & 3, wn = warp >> 2;
    const int row0 = blockIdx.x * 64;

    const int ar = tid >> 2, ac = (tid & 3) << 3;        // A: 64 rows x 4 chunks of 8 halves
    const int br = tid >> 4, bc = (tid & 15) << 3;       // B: rows br and br+16, 16 chunks/row

    wmma::fragment<wmma::accumulator, 16, 16, 16, float> acc[4];
#pragma unroll
    for (int j = 0; j < 4; j++) wmma::fill_fragment(acc[j], 0.f);

    auto load_stage = [&](int slot, int k0) {
        __half* a = As + slot * A_STAGE;
        __half* b = Bs + slot * B_STAGE;
        bool va = (row0 + ar) < NW && (k0 + ac) < NW;
        cpa16(a + ar * 40 + ac, g_A16 + (size_t)(row0 + ar) * NW + k0 + ac, va);
        cpa16(b + br * 136 + bc, cat + (size_t)(k0 + br) * 384 + bcol + bc, (k0 + br) < NW);
        cpa16(b + (br + 16) * 136 + bc, cat + (size_t)(k0 + br + 16) * 384 + bcol + bc,
              (k0 + br + 16) < NW);
    };

    const int nk = (NW + 31) / 32;  // 313
#pragma unroll
    for (int s = 0; s < STAGES - 1; s++) {
        load_stage(s, s * 32);
        asm volatile("cp.async.commit_group;\n");
    }

    for (int i = 0; i < nk; i++) {
        asm volatile("cp.async.wait_group %0;\n" :: "n"(STAGES - 2));
        __syncthreads();

        int nx = i + STAGES - 1;
        if (nx < nk) load_stage(nx % STAGES, nx * 32);
        asm volatile("cp.async.commit_group;\n");   // always commit (empty groups keep count)

        const __half* Ab = As + (i % STAGES) * A_STAGE;
        const __half* Bb = Bs + (i % STAGES) * B_STAGE;
#pragma unroll
        for (int kk = 0; kk < 32; kk += 16) {
            wmma::fragment<wmma::matrix_a, 16, 16, 16, __half, wmma::row_major> af;
            wmma::load_matrix_sync(af, Ab + (wm * 16) * 40 + kk, 40);
#pragma unroll
            for (int j = 0; j < 4; j++) {
                wmma::fragment<wmma::matrix_b, 16, 16, 16, __half, wmma::row_major> bf;
                wmma::load_matrix_sync(bf, Bb + kk * 136 + wn * 64 + j * 16, 136);
                wmma::mma_sync(acc[j], af, bf, acc[j]);
            }
        }
    }

    asm volatile("cp.async.wait_group 0;\n");
    __syncthreads();   // smem now reusable as epilogue buffer

    float* Cw = (float*)raw + warp * 1024;               // 16x64 patch per warp
    wmma::store_matrix_sync(Cw +  0, acc[0], 64, wmma::mem_row_major);
    wmma::store_matrix_sync(Cw + 16, acc[1], 64, wmma::mem_row_major);
    wmma::store_matrix_sync(Cw + 32, acc[2], 64, wmma::mem_row_major);
    wmma::store_matrix_sync(Cw + 48, acc[3], 64, wmma::mem_row_major);
    __syncwarp();

    const float sc = 1.f / 256.f;
#pragma unroll
    for (int r = 0; r < 16; r++) {
        int grow = row0 + wm * 16 + r;
        if (grow >= NW) continue;
        int gcol = wn * 64 + lane * 2;
        float v0 = Cw[r * 64 + lane * 2] * sc;
        float v1 = Cw[r * 64 + lane * 2 + 1] * sc;
        if (ucol >= 0) {
            __half2 u = *(const __half2*)(cat + (size_t)grow * 384 + ucol + gcol);
            v0 = 2.f * v0 - __half2float(__low2half(u));
            v1 = 2.f * v1 - __half2float(__high2half(u));
        }
        *(__half2*)(cat + (size_t)grow * 384 + ccol + gcol) = __floats2half2_rn(v0, v1);
    }
}

// ---------------- gate GEMM: cat1 @ Wg + bias -> sigmoid; builds cat2 prefix ----------------
__global__ void wgemmGates(const __half* __restrict__ cat1, __half* __restrict__ cat2,
                           const float* __restrict__ W, const float* __restrict__ bias,
                           int D, int dec) {
    __shared__ __align__(16) __half cs[8][384];
    int tid = threadIdx.x;
    int row0 = blockIdx.x * 8;
    const float4* src = (const float4*)(cat1 + (size_t)row0 * 384);
    float4* dst = (float4*)&cs[0][0];
    for (int i = tid; i < 384; i += 128) dst[i] = src[i];
    __syncthreads();

    float v[8];
#pragma unroll
    for (int r = 0; r < 8; r++) v[r] = 0.f;
    int col = tid;
    for (int g = 0; g < 3; g++)
        for (int kk = 0; kk < D; kk++) {
            float w = W[(size_t)(g * D + kk) * 128 + col];
            int cc = g * 128 + kk;
#pragma unroll
            for (int r = 0; r < 8; r++) v[r] += __half2float(cs[r][cc]) * w;
        }
    float b = bias[col];
#pragma unroll
    for (int r = 0; r < 8; r++) {
        int row = row0 + r;
        float gate = 1.f / (1.f + __expf(-(v[r] + b)));
        if (col < 64) {
            float rh = gate * g_h[row * 64 + col];
            if (!dec) {
                cat2[(size_t)row * 384 + 64 + col] = __float2half(rh);
                cat2[(size_t)row * 384 + col] = cs[r][col];
            } else {
                cat2[(size_t)row * 384 + 1 + col] = __float2half(rh);
                if (col == 0) cat2[(size_t)row * 384] = cs[r][0];
            }
        } else {
            g_u[row * 64 + (col - 64)] = gate;
            if (dec && col > 64) cat2[(size_t)row * 384 + col] = __float2half(0.f);
        }
    }
}

// ---------------- candidate GEMM + GRU update ----------------
__global__ void wgemmCand(const __half* __restrict__ cat2, const float* __restrict__ W,
                          const float* __restrict__ bias, int D) {
    __shared__ __align__(16) __half cs[8][384];
    int tid = threadIdx.x;
    int row0 = blockIdx.x * 8;
    const float4* src = (const float4*)(cat2 + (size_t)row0 * 384);
    float4* dst = (float4*)&cs[0][0];
    for (int i = tid; i < 384; i += 64) dst[i] = src[i];
    __syncthreads();

    float v[8];
#pragma unroll
    for (int r = 0; r < 8; r++) v[r] = 0.f;
    int col = tid;
    for (int g = 0; g < 3; g++)
        for (int kk = 0; kk < D; kk++) {
            float w = W[(size_t)(g * D + kk) * 64 + col];
            int cc = g * 128 + kk;
#pragma unroll
            for (int r = 0; r < 8; r++) v[r] += __half2float(cs[r][cc]) * w;
        }
    float b = bias[col];
#pragma unroll
    for (int r = 0; r < 8; r++) {
        int row = row0 + r;
        float c = tanhf(v[r] + b);
        float u = g_u[row * 64 + col];
        float hOld = g_h[row * 64 + col];
        g_h[row * 64 + col] = u * hOld + (1.f - u) * c;
    }
}

// ---------------- prediction ----------------
__global__ void predKernel(const float* __restrict__ Wp, const float* __restrict__ bp,
                           float* __restrict__ out, int t) {
    int gwarp = (blockIdx.x * blockDim.x + threadIdx.x) >> 5;
    int lane = threadIdx.x & 31;
    if (gwarp >= NW) return;
    float s = g_h[gwarp * 64 + lane] * Wp[lane] + g_h[gwarp * 64 + 32 + lane] * Wp[32 + lane];
#pragma unroll
    for (int o = 16; o; o >>= 1) s += __shfl_xor_sync(0xFFFFFFFFu, s, o);
    if (lane == 0) {
        float val = s + bp[0];
        out[gwarp * 12 + t] = val;
        g_x[gwarp] = val;
    }
}

// ---------------- launch ----------------
extern "C" void kernel_launch(void* const* d_in, const int* in_sizes, int n_in,
                              void* d_out, int out_size) {
    const float* inputs = (const float*)d_in[0];
    const float* adj    = (const float*)d_in[2];
    const float* W_emb  = (const float*)d_in[3];
    const float* b_emb  = (const float*)d_in[4];
    const float* Wg_e   = (const float*)d_in[5];
    const float* bg_e   = (const float*)d_in[6];
    const float* Wc_e   = (const float*)d_in[7];
    const float* bc_e   = (const float*)d_in[8];
    const float* Wg_d   = (const float*)d_in[9];
    const float* bg_d   = (const float*)d_in[10];
    const float* Wc_d   = (const float*)d_in[11];
    const float* bc_d   = (const float*)d_in[12];
    const float* W_pred = (const float*)d_in[13];
    const float* b_pred = (const float*)d_in[14];
    float* out = (float*)d_out;

    __half *cat1, *cat2;
    cudaGetSymbolAddress((void**)&cat1, g_cat1);
    cudaGetSymbolAddress((void**)&cat2, g_cat2);

    const int smem = STAGES * (A_STAGE + B_STAGE) * 2;  // 55296 B
    cudaFuncSetAttribute(bigGemm, cudaFuncAttributeMaxDynamicSharedMemorySize, smem);

    convA<<<1184, 256>>>(adj);
    initState<<<(NW * HIDW + 255) / 256, 256>>>();

    int bg_grid = 157;
    int build_grid = (NW * 128 + 255) / 256;

    for (int t = 0; t < 12; t++) {
        encBuild<<<build_grid, 256>>>(inputs, W_emb, b_emb, t);
        bigGemm<<<bg_grid, 256, smem>>>(cat1, 0, 128, -1);
        bigGemm<<<bg_grid, 256, smem>>>(cat1, 128, 256, 0);
        wgemmGates<<<NW / 8, 128>>>(cat1, cat2, Wg_e, bg_e, 128, 0);
        bigGemm<<<bg_grid, 256, smem>>>(cat2, 0, 128, -1);
        bigGemm<<<bg_grid, 256, smem>>>(cat2, 128, 256, 0);
        wgemmCand<<<NW / 8, 64>>>(cat2, Wc_e, bc_e, 128);
    }
    for (int t = 0; t < 12; t++) {
        decBuild<<<build_grid, 256>>>();
        bigGemm<<<bg_grid, 256, smem>>>(cat1, 0, 128, -1);
        bigGemm<<<bg_grid, 256, smem>>>(cat1, 128, 256, 0);
        wgemmGates<<<NW / 8, 128>>>(cat1, cat2, Wg_d, bg_d, 65, 1);
        bigGemm<<<bg_grid, 256, smem>>>(cat2, 0, 128, -1);
        bigGemm<<<bg_grid, 256, smem>>>(cat2, 128, 256, 0);
        wgemmCand<<<NW / 8, 64>>>(cat2, Wc_d, bc_d, 65);
        predKernel<<<(NW + 3) / 4, 128>>>(W_pred, b_pred, out, t);
    }
}

// round 6
// speedup vs baseline: 1.9169x; 1.3527x over previous
#include <cuda_runtime.h>
#include <cuda_fp16.h>
#include <mma.h>
#include <math.h>
#include <stdint.h>

using namespace nvcuda;

#define NW 10000
#define NKB 157                 // 64-wide blocks covering 10048 (rows and k)
#define A_TILE_H 4608           // 64 rows * 72 halves
#define B_TILE_H 8704           // 64 rows * 136 halves
#define SEC_H (NKB * B_TILE_H)  // halves per panel section
#define STAGES 3
#define SLOT_BYTES 26624        // 9216 (A) + 17408 (B)

// ---------------- device scratch (static, allocation-free) ----------------
__device__ __align__(16) __half g_A16[(size_t)NKB * NKB * A_TILE_H]; // tiled A, x256
__device__ __align__(16) __half g_cat1[3 * SEC_H];  // sections: u, x1, x2 (tiled)
__device__ __align__(16) __half g_cat2[3 * SEC_H];
__device__ float g_h[NW * 64];
__device__ float g_u[NW * 64];
__device__ float g_x[NW];

// tiled panel index: node n, feature f -> halves offset within a section
__device__ __forceinline__ size_t pidx(int n, int f) {
    return (size_t)(n >> 6) * B_TILE_H + (size_t)(n & 63) * 136 + f;
}

// ---------------- A conversion into tiled, padded, scaled layout ----------------
__global__ void convA(const float* __restrict__ A) {
    size_t total = (size_t)NKB * NKB * 2048;  // half2 per tile = 64*32
    for (size_t j = (size_t)blockIdx.x * blockDim.x + threadIdx.x; j < total;
         j += (size_t)gridDim.x * blockDim.x) {
        size_t tile = j >> 11;
        int within = (int)(j & 2047);
        int r = within >> 5, c2 = within & 31;
        int rb = (int)(tile / NKB), kb = (int)(tile % NKB);
        int row = rb * 64 + r, k = kb * 64 + c2 * 2;
        __half2 v = __floats2half2_rn(0.f, 0.f);
        if (row < NW && k + 1 < NW) {
            float2 f = *(const float2*)(A + (size_t)row * NW + k);
            v = __floats2half2_rn(f.x * 256.f, f.y * 256.f);
        }
        *(__half2*)(g_A16 + tile * A_TILE_H + r * 72 + c2 * 2) = v;
    }
}

__global__ void initState() {
    int idx = blockIdx.x * blockDim.x + threadIdx.x;
    if (idx < NW * 64) g_h[idx] = 0.f;
    if (idx < NW) g_x[idx] = 0.f;
    // zero pad node rows 10000..10047 in all 6 sections (48 nodes x 136 feats)
    if (idx < 2 * 3 * 48 * 136) {
        int a = idx / (3 * 48 * 136);
        int rem = idx % (3 * 48 * 136);
        int s = rem / (48 * 136);
        int rem2 = rem % (48 * 136);
        int n = NW + rem2 / 136;
        int f = rem2 % 136;
        __half* cat = a ? g_cat2 : g_cat1;
        cat[(size_t)s * SEC_H + pidx(n, f)] = __float2half(0.f);
    }
}

// ---------------- builds (write tiled u-section) ----------------
__global__ void encBuild(const float* __restrict__ inputs, const float* __restrict__ W_emb,
                         const float* __restrict__ b_emb, int t) {
    int idx = blockIdx.x * blockDim.x + threadIdx.x;
    if (idx >= NW * 128) return;
    int row = idx >> 7, c = idx & 127;
    float v;
    if (c < 64) v = inputs[row * 12 + t] * W_emb[c] + b_emb[c];
    else        v = g_h[row * 64 + (c - 64)];
    g_cat1[pidx(row, c)] = __float2half(v);
}

__global__ void decBuild() {
    int idx = blockIdx.x * blockDim.x + threadIdx.x;
    if (idx >= NW * 128) return;
    int row = idx >> 7, c = idx & 127;
    float v = 0.f;
    if (c == 0)      v = g_x[row];
    else if (c < 65) v = g_h[row * 64 + (c - 1)];
    g_cat1[pidx(row, c)] = __float2half(v);
}

// ---------------- bulk copy + mbarrier helpers ----------------
__device__ __forceinline__ void bulkcp(void* sdst, const void* gsrc, uint32_t bytes, uint32_t mbar) {
    uint32_t d = (uint32_t)__cvta_generic_to_shared(sdst);
    asm volatile(
        "cp.async.bulk.shared::cluster.global.mbarrier::complete_tx::bytes [%0], [%1], %2, [%3];"
        :: "r"(d), "l"(gsrc), "r"(bytes), "r"(mbar) : "memory");
}
__device__ __forceinline__ void mbar_init(uint32_t mbar, uint32_t cnt) {
    asm volatile("mbarrier.init.shared.b64 [%0], %1;" :: "r"(mbar), "r"(cnt) : "memory");
}
__device__ __forceinline__ void mbar_expect(uint32_t mbar, uint32_t bytes) {
    asm volatile("mbarrier.arrive.expect_tx.shared.b64 _, [%0], %1;" :: "r"(mbar), "r"(bytes) : "memory");
}
__device__ __forceinline__ void mbar_wait(uint32_t mbar, uint32_t parity) {
    asm volatile(
        "{\n\t.reg .pred P;\n\t"
        "W%=:\n\t"
        "mbarrier.try_wait.parity.acquire.cta.shared::cta.b64 P, [%0], %1, 0x989680;\n\t"
        "@P bra D%=;\n\t"
        "bra W%=;\n\t"
        "D%=:\n\t}"
        :: "r"(mbar), "r"(parity) : "memory");
}

// ---------------- big GEMM: A_tiled @ panel ----------------
// BM=64, BN=128, BK=64. 3-stage cp.async.bulk pipeline, 8 warps (4x2), warp tile 16x64.
// Usec != null => out = 2*(acc/256) - U (Chebyshev), else out = acc/256. Output tiled.
__global__ void __launch_bounds__(256) bigGemm(const __half* __restrict__ Bsec,
                                               __half* __restrict__ Csec,
                                               const __half* __restrict__ Usec) {
    extern __shared__ __align__(16) char raw[];
    __shared__ __align__(8) uint64_t mbar[STAGES];
    const int tid = threadIdx.x, warp = tid >> 5, lane = tid & 31;
    const int wm = warp & 3, wn = warp >> 2;
    const int row0 = blockIdx.x * 64;
    const __half* Atiles = g_A16 + (size_t)blockIdx.x * NKB * A_TILE_H;

    if (tid == 0)
        for (int s = 0; s < STAGES; s++)
            mbar_init((uint32_t)__cvta_generic_to_shared(&mbar[s]), 1);
    __syncthreads();

    auto fill = [&](int slot, int kb) {
        uint32_t mb = (uint32_t)__cvta_generic_to_shared(&mbar[slot]);
        mbar_expect(mb, SLOT_BYTES);
        bulkcp(raw + slot * SLOT_BYTES, Atiles + (size_t)kb * A_TILE_H, 9216, mb);
        bulkcp(raw + slot * SLOT_BYTES + 9216, Bsec + (size_t)kb * B_TILE_H, 17408, mb);
    };

    if (tid == 0) { fill(0, 0); fill(1, 1); }

    wmma::fragment<wmma::accumulator, 16, 16, 16, float> acc[4];
#pragma unroll
    for (int j = 0; j < 4; j++) wmma::fill_fragment(acc[j], 0.f);

    for (int i = 0; i < NKB; i++) {
        __syncthreads();                       // everyone done with slot (i+2)%3's last round
        if (tid == 0 && i + STAGES - 1 < NKB) fill((i + STAGES - 1) % STAGES, i + STAGES - 1);

        int slot = i % STAGES;
        mbar_wait((uint32_t)__cvta_generic_to_shared(&mbar[slot]), (uint32_t)((i / STAGES) & 1));

        const __half* As = (const __half*)(raw + slot * SLOT_BYTES);
        const __half* Bs = (const __half*)(raw + slot * SLOT_BYTES + 9216);
#pragma unroll
        for (int kk = 0; kk < 64; kk += 16) {
            wmma::fragment<wmma::matrix_a, 16, 16, 16, __half, wmma::row_major> af;
            wmma::load_matrix_sync(af, As + (wm * 16) * 72 + kk, 72);
#pragma unroll
            for (int j = 0; j < 4; j++) {
                wmma::fragment<wmma::matrix_b, 16, 16, 16, __half, wmma::row_major> bf;
                wmma::load_matrix_sync(bf, Bs + kk * 136 + wn * 64 + j * 16, 136);
                wmma::mma_sync(acc[j], af, bf, acc[j]);
            }
        }
    }
    __syncthreads();   // protect smem reuse below

    float* Cw = (float*)raw + warp * 1024;   // 16x64 patch per warp
    wmma::store_matrix_sync(Cw +  0, acc[0], 64, wmma::mem_row_major);
    wmma::store_matrix_sync(Cw + 16, acc[1], 64, wmma::mem_row_major);
    wmma::store_matrix_sync(Cw + 32, acc[2], 64, wmma::mem_row_major);
    wmma::store_matrix_sync(Cw + 48, acc[3], 64, wmma::mem_row_major);
    __syncwarp();

    const float sc = 1.f / 256.f;
#pragma unroll
    for (int r = 0; r < 16; r++) {
        int grow = row0 + wm * 16 + r;
        if (grow >= NW) continue;
        int gcol = wn * 64 + lane * 2;
        float v0 = Cw[r * 64 + lane * 2] * sc;
        float v1 = Cw[r * 64 + lane * 2 + 1] * sc;
        if (Usec) {
            __half2 u = *(const __half2*)(Usec + pidx(grow, gcol));
            v0 = 2.f * v0 - __half2float(__low2half(u));
            v1 = 2.f * v1 - __half2float(__high2half(u));
        }
        *(__half2*)(Csec + pidx(grow, gcol)) = __floats2half2_rn(v0, v1);
    }
}

// ---------------- gate GEMM: [u|x1|x2] @ Wg + bias -> sigmoid; builds cat2 u-section ----------------
__global__ void wgemmGates(const __half* __restrict__ cat1, __half* __restrict__ cat2,
                           const float* __restrict__ W, const float* __restrict__ bias,
                           int D, int dec) {
    __shared__ __align__(16) __half cs[8][384];
    int tid = threadIdx.x;
    int row0 = blockIdx.x * 8;
    for (int i = tid; i < 384; i += 128) {            // 8 nodes x 3 secs x 16 float4
        int r = i / 48, rem = i % 48;
        int s = rem / 16, q = rem % 16;
        int node = row0 + r;
        const float4* src = (const float4*)(cat1 + (size_t)s * SEC_H + pidx(node, 0));
        *(float4*)&cs[r][s * 128 + q * 8] = src[q];
    }
    __syncthreads();

    float v[8];
#pragma unroll
    for (int r = 0; r < 8; r++) v[r] = 0.f;
    int col = tid;
    for (int g = 0; g < 3; g++)
        for (int kk = 0; kk < D; kk++) {
            float w = W[(size_t)(g * D + kk) * 128 + col];
            int cc = g * 128 + kk;
#pragma unroll
            for (int r = 0; r < 8; r++) v[r] += __half2float(cs[r][cc]) * w;
        }
    float b = bias[col];
#pragma unroll
    for (int r = 0; r < 8; r++) {
        int row = row0 + r;
        float gate = 1.f / (1.f + __expf(-(v[r] + b)));
        if (col < 64) {
            float rh = gate * g_h[row * 64 + col];
            if (!dec) {
                cat2[pidx(row, 64 + col)] = __float2half(rh);
                cat2[pidx(row, col)] = cs[r][col];
            } else {
                cat2[pidx(row, 1 + col)] = __float2half(rh);
                if (col == 0) cat2[pidx(row, 0)] = cs[r][0];
            }
        } else {
            g_u[row * 64 + (col - 64)] = gate;
            if (dec && col > 64) cat2[pidx(row, col)] = __float2half(0.f);
        }
    }
}

// ---------------- candidate GEMM + GRU update ----------------
__global__ void wgemmCand(const __half* __restrict__ cat2, const float* __restrict__ W,
                          const float* __restrict__ bias, int D) {
    __shared__ __align__(16) __half cs[8][384];
    int tid = threadIdx.x;
    int row0 = blockIdx.x * 8;
    for (int i = tid; i < 384; i += 64) {
        int r = i / 48, rem = i % 48;
        int s = rem / 16, q = rem % 16;
        int node = row0 + r;
        const float4* src = (const float4*)(cat2 + (size_t)s * SEC_H + pidx(node, 0));
        *(float4*)&cs[r][s * 128 + q * 8] = src[q];
    }
    __syncthreads();

    float v[8];
#pragma unroll
    for (int r = 0; r < 8; r++) v[r] = 0.f;
    int col = tid;
    for (int g = 0; g < 3; g++)
        for (int kk = 0; kk < D; kk++) {
            float w = W[(size_t)(g * D + kk) * 64 + col];
            int cc = g * 128 + kk;
#pragma unroll
            for (int r = 0; r < 8; r++) v[r] += __half2float(cs[r][cc]) * w;
        }
    float b = bias[col];
#pragma unroll
    for (int r = 0; r < 8; r++) {
        int row = row0 + r;
        float c = tanhf(v[r] + b);
        float u = g_u[row * 64 + col];
        float hOld = g_h[row * 64 + col];
        g_h[row * 64 + col] = u * hOld + (1.f - u) * c;
    }
}

// ---------------- prediction ----------------
__global__ void predKernel(const float* __restrict__ Wp, const float* __restrict__ bp,
                           float* __restrict__ out, int t) {
    int gwarp = (blockIdx.x * blockDim.x + threadIdx.x) >> 5;
    int lane = threadIdx.x & 31;
    if (gwarp >= NW) return;
    float s = g_h[gwarp * 64 + lane] * Wp[lane] + g_h[gwarp * 64 + 32 + lane] * Wp[32 + lane];
#pragma unroll
    for (int o = 16; o; o >>= 1) s += __shfl_xor_sync(0xFFFFFFFFu, s, o);
    if (lane == 0) {
        float val = s + bp[0];
        out[gwarp * 12 + t] = val;
        g_x[gwarp] = val;
    }
}

// ---------------- launch ----------------
extern "C" void kernel_launch(void* const* d_in, const int* in_sizes, int n_in,
                              void* d_out, int out_size) {
    const float* inputs = (const float*)d_in[0];
    const float* adj    = (const float*)d_in[2];
    const float* W_emb  = (const float*)d_in[3];
    const float* b_emb  = (const float*)d_in[4];
    const float* Wg_e   = (const float*)d_in[5];
    const float* bg_e   = (const float*)d_in[6];
    const float* Wc_e   = (const float*)d_in[7];
    const float* bc_e   = (const float*)d_in[8];
    const float* Wg_d   = (const float*)d_in[9];
    const float* bg_d   = (const float*)d_in[10];
    const float* Wc_d   = (const float*)d_in[11];
    const float* bc_d   = (const float*)d_in[12];
    const float* W_pred = (const float*)d_in[13];
    const float* b_pred = (const float*)d_in[14];
    float* out = (float*)d_out;

    __half *cat1, *cat2;
    cudaGetSymbolAddress((void**)&cat1, g_cat1);
    cudaGetSymbolAddress((void**)&cat2, g_cat2);
    __half* c1s0 = cat1;            __half* c1s1 = cat1 + SEC_H;  __half* c1s2 = cat1 + 2 * SEC_H;
    __half* c2s0 = cat2;            __half* c2s1 = cat2 + SEC_H;  __half* c2s2 = cat2 + 2 * SEC_H;

    const int smem = STAGES * SLOT_BYTES;  // 79872
    cudaFuncSetAttribute(bigGemm, cudaFuncAttributeMaxDynamicSharedMemorySize, smem);

    convA<<<4096, 256>>>(adj);
    initState<<<(NW * 64 + 255) / 256, 256>>>();

    int build_grid = (NW * 128 + 255) / 256;

    for (int t = 0; t < 12; t++) {
        encBuild<<<build_grid, 256>>>(inputs, W_emb, b_emb, t);
        bigGemm<<<NKB, 256, smem>>>(c1s0, c1s1, (const __half*)nullptr);
        bigGemm<<<NKB, 256, smem>>>(c1s1, c1s2, c1s0);
        wgemmGates<<<NW / 8, 128>>>(cat1, cat2, Wg_e, bg_e, 128, 0);
        bigGemm<<<NKB, 256, smem>>>(c2s0, c2s1, (const __half*)nullptr);
        bigGemm<<<NKB, 256, smem>>>(c2s1, c2s2, c2s0);
        wgemmCand<<<NW / 8, 64>>>(cat2, Wc_e, bc_e, 128);
    }
    for (int t = 0; t < 12; t++) {
        decBuild<<<build_grid, 256>>>();
        bigGemm<<<NKB, 256, smem>>>(c1s0, c1s1, (const __half*)nullptr);
        bigGemm<<<NKB, 256, smem>>>(c1s1, c1s2, c1s0);
        wgemmGates<<<NW / 8, 128>>>(cat1, cat2, Wg_d, bg_d, 65, 1);
        bigGemm<<<NKB, 256, smem>>>(c2s0, c2s1, (const __half*)nullptr);
        bigGemm<<<NKB, 256, smem>>>(c2s1, c2s2, c2s0);
        wgemmCand<<<NW / 8, 64>>>(cat2, Wc_d, bc_d, 65);
        predKernel<<<(NW + 3) / 4, 128>>>(W_pred, b_pred, out, t);
    }
}